// round 10
// baseline (speedup 1.0000x reference)
#include <cuda_runtime.h>
#include <math.h>

#define SS 512
#define DD 768
#define HH 12
#define HDD 64
#define RR 16
#define GAUGE_ELEMS (HH*SS*SS)   // 3,145,728

typedef unsigned long long ull;

// ---------------- scratch (device globals; no allocation allowed) ------------
__device__ float g_h[SS*RR];                // [s][r]
__device__ float g_Aq[HH*SS*HDD];           // [h][s][d]
__device__ float g_Ak[HH*SS*HDD];
__device__ float g_Mq[HH*HDD*RR];           // [h][d][r]  = Wq @ W2q_h
__device__ float g_Mk[HH*HDD*RR];           // [h][d][r]  = Wk @ W2k_h
__device__ float g_Mv[DD*RR];               // [c][r]     = Wv @ W2v
__device__ float g_P[HH*SS*RR];             // [h][s][r]  = q_base @ Mk
__device__ float g_Q[HH*SS*RR];             // [h][s][r]  = k_base @ Mq
__device__ unsigned g_maxbits;

// degree-9 odd Taylor for tanh: exact to ~1e-5 for |x| <= 0.5
#define C3 (-0.333333333f)
#define C5 ( 0.133333333f)
#define C7 (-0.053968254f)
#define C9 ( 0.021869489f)

// ---------------- packed f32x2 helpers (sm_103a dual-fp32) -------------------
__device__ __forceinline__ ull pk2(float lo, float hi) {
    ull r; asm("mov.b64 %0,{%1,%2};" : "=l"(r) : "f"(lo), "f"(hi)); return r;
}
__device__ __forceinline__ void upk2(ull v, float& lo, float& hi) {
    asm("mov.b64 {%0,%1},%2;" : "=f"(lo), "=f"(hi) : "l"(v));
}
__device__ __forceinline__ ull fma2(ull a, ull b, ull c) {
    ull d; asm("fma.rn.f32x2 %0,%1,%2,%3;" : "=l"(d) : "l"(a), "l"(b), "l"(c)); return d;
}
__device__ __forceinline__ ull add2(ull a, ull b) {
    ull d; asm("add.rn.f32x2 %0,%1,%2;" : "=l"(d) : "l"(a), "l"(b)); return d;
}
__device__ __forceinline__ ull mul2(ull a, ull b) {
    ull d; asm("mul.rn.f32x2 %0,%1,%2;" : "=l"(d) : "l"(a), "l"(b)); return d;
}

// ------------------- K1: LayerNorm + h = silu(x @ W1^T) ---------------------
__global__ void k_ln_h(const float* __restrict__ hs, const float* __restrict__ gamma,
                       const float* __restrict__ beta, const float* __restrict__ W1) {
    int s = blockIdx.x, tid = threadIdx.x;
    if (blockIdx.x == 0 && tid == 0) g_maxbits = 0u;
    __shared__ float xs[DD];
    __shared__ float red[20];
    const float* row = hs + s*DD;
    float v0 = row[tid], v1 = row[tid+256], v2 = row[tid+512];
    float sum = v0+v1+v2, sq = v0*v0 + v1*v1 + v2*v2;
    #pragma unroll
    for (int o = 16; o; o >>= 1) {
        sum += __shfl_xor_sync(0xffffffffu, sum, o);
        sq  += __shfl_xor_sync(0xffffffffu, sq,  o);
    }
    int wid = tid >> 5, lid = tid & 31;
    if (lid == 0) { red[wid] = sum; red[wid+8] = sq; }
    __syncthreads();
    if (tid == 0) {
        float Sm = 0.f, Q = 0.f;
        for (int w = 0; w < 8; w++) { Sm += red[w]; Q += red[w+8]; }
        float mu  = Sm * (1.f/DD);
        float var = Q  * (1.f/DD) - mu*mu;
        red[16] = mu; red[17] = rsqrtf(var + 1e-5f);
    }
    __syncthreads();
    float mu = red[16], ri = red[17];
    xs[tid]     = (v0-mu)*ri*gamma[tid]     + beta[tid];
    xs[tid+256] = (v1-mu)*ri*gamma[tid+256] + beta[tid+256];
    xs[tid+512] = (v2-mu)*ri*gamma[tid+512] + beta[tid+512];
    __syncthreads();
    int r0 = wid * 2;
    float a0 = 0.f, a1 = 0.f;
    for (int e = lid; e < DD; e += 32) {
        float xv = xs[e];
        a0 = fmaf(xv, W1[r0*DD + e],     a0);
        a1 = fmaf(xv, W1[(r0+1)*DD + e], a1);
    }
    #pragma unroll
    for (int o = 16; o; o >>= 1) {
        a0 += __shfl_xor_sync(0xffffffffu, a0, o);
        a1 += __shfl_xor_sync(0xffffffffu, a1, o);
    }
    if (lid == 0) {
        g_h[s*RR + r0]     = a0 / (1.f + expf(-a0));
        g_h[s*RR + r0 + 1] = a1 / (1.f + expf(-a1));
    }
}

// ------- K2: merged weight products Mq, Mk (per head) and Mv (weights only) --
__global__ void k_merge(const float* __restrict__ Wq, const float* __restrict__ Wk,
                        const float* __restrict__ Wv, const float* __restrict__ W2) {
    int b = blockIdx.x, tid = threadIdx.x;
    if (b < 24) {
        // Mq (b<12) or Mk (b>=12): M[h][d][r] = sum_e W[d][e] * W2[off + h*64 + e][r]
        int h = (b < 12) ? b : b - 12;
        const float* Wx = (b < 12) ? Wq : Wk;
        float* dst = (b < 12) ? g_Mq : g_Mk;
        int w2off = (b < 12) ? 0 : 768;
        __shared__ float sW2[HDD*RR];   // [e][r]
        for (int idx = tid; idx < HDD*RR; idx += 256)
            sW2[idx] = W2[(size_t)(w2off + h*HDD + (idx >> 4))*RR + (idx & 15)];
        __syncthreads();
        for (int o = tid; o < HDD*RR; o += 256) {
            int d = o >> 4, r = o & 15;
            float acc = 0.f;
            #pragma unroll 8
            for (int e = 0; e < HDD; e++)
                acc = fmaf(Wx[d*HDD + e], sW2[e*RR + r], acc);
            dst[h*HDD*RR + o] = acc;
        }
    } else {
        // Mv: 48 blocks x 16 c-rows; Mv[c][r] = sum_e Wv[c][e] * W2[1536+e][r]
        int c0 = (b - 24) * 16;
        int c = c0 + (tid >> 4), r = tid & 15;
        float acc = 0.f;
        #pragma unroll 4
        for (int e = 0; e < DD; e++)
            acc = fmaf(Wv[(size_t)c*DD + e], W2[(size_t)(1536 + e)*RR + r], acc);
        g_Mv[c*RR + r] = acc;
    }
}

// -------- K3: A_q/A_k = h @ W2qk^T (head-major) + max|A|, delta_v fused -----
__global__ void k_fieldA(const float* __restrict__ W2, const float* __restrict__ gval,
                         float* __restrict__ out_dv) {
    int s = blockIdx.x, tid = threadIdx.x;
    __shared__ float hsh[RR];
    __shared__ float wmax[8];
    if (tid < RR) hsh[tid] = g_h[s*RR + tid];
    __syncthreads();
    float h0=hsh[0],h1=hsh[1],h2=hsh[2],h3=hsh[3],h4=hsh[4],h5=hsh[5],h6=hsh[6],h7=hsh[7];
    float h8=hsh[8],h9=hsh[9],hA=hsh[10],hB=hsh[11],hC=hsh[12],hD=hsh[13],hE=hsh[14],hF=hsh[15];
    float mx = 0.f;
    #pragma unroll
    for (int it = 0; it < 9; it++) {
        int c = it*256 + tid;
        const float* wrow = (c < 1536) ? (W2 + (size_t)c*RR) : (g_Mv + (size_t)(c-1536)*RR);
        const float4* wr = reinterpret_cast<const float4*>(wrow);
        float4 w0 = wr[0], w1 = wr[1], w2 = wr[2], w3 = wr[3];
        float acc = h0*w0.x + h1*w0.y + h2*w0.z + h3*w0.w
                  + h4*w1.x + h5*w1.y + h6*w1.z + h7*w1.w
                  + h8*w2.x + h9*w2.y + hA*w2.z + hB*w2.w
                  + hC*w3.x + hD*w3.y + hE*w3.z + hF*w3.w;
        if (c < 768) {
            int hh = c >> 6, d = c & 63;
            g_Aq[(hh*SS + s)*HDD + d] = acc;
            mx = fmaxf(mx, fabsf(acc));
        } else if (c < 1536) {
            int cc = c - 768; int hh = cc >> 6, d = cc & 63;
            g_Ak[(hh*SS + s)*HDD + d] = acc;
            mx = fmaxf(mx, fabsf(acc));
        } else {
            int cc = c - 1536;
            out_dv[(size_t)s*DD + cc] = tanhf(gval[cc]) * acc;
        }
    }
    #pragma unroll
    for (int o = 16; o; o >>= 1) mx = fmaxf(mx, __shfl_xor_sync(0xffffffffu, mx, o));
    if ((tid & 31) == 0) wmax[tid >> 5] = mx;
    __syncthreads();
    if (tid == 0) {
        float m = wmax[0];
        for (int w = 1; w < 8; w++) m = fmaxf(m, wmax[w]);
        atomicMax(&g_maxbits, __float_as_uint(m));
    }
}

// -------- K4: P = q_base @ Mk ; Q = k_base @ Mq (rank-16 projections) -------
__global__ void k_pq(const float* __restrict__ qb, const float* __restrict__ kb) {
    int h = blockIdx.y, s0 = blockIdx.x * 16, tid = threadIdx.x;
    __shared__ float sMk[HDD*RR], sMq[HDD*RR];
    for (int idx = tid; idx < HDD*RR; idx += 256) {
        sMk[idx] = g_Mk[h*HDD*RR + idx];
        sMq[idx] = g_Mq[h*HDD*RR + idx];
    }
    __syncthreads();
    int i = tid >> 4, r = tid & 15;
    int s = s0 + i;
    const float* qrow = qb + (size_t)(h*SS + s)*HDD;
    const float* krow = kb + (size_t)(h*SS + s)*HDD;
    float accP = 0.f, accQ = 0.f;
    #pragma unroll 8
    for (int d = 0; d < HDD; d++) {
        accP = fmaf(qrow[d], sMk[d*RR + r], accP);
        accQ = fmaf(krow[d], sMq[d*RR + r], accQ);
    }
    g_P[(h*SS + s)*RR + r] = accP;
    g_Q[(h*SS + s)*RR + r] = accQ;
}

// ---- K5: gauge[h,i,j] = ca*(b1+b2) + cr*b3, f32x2-packed, 64x64 tiles ------
#define PADJ 66
__global__ __launch_bounds__(128, 3)
void k_gauge(const float* __restrict__ rbv, const float* __restrict__ gat,
             const float* __restrict__ grl, float* __restrict__ out) {
    extern __shared__ float sm[];
    float* sQa = sm;                    // [64][66]  A_q, d-major over i
    float* sKa = sQa + 64*PADJ;         // [64][66]  A_k, d-major over j
    float* sPi = sKa + 64*PADJ;         // [16][64]  P,  r-major over i
    float* sHi = sPi + 16*64;           // [16][64]  h,  r-major over i
    float* sQj = sHi + 16*64;           // [16][66]  Q,  r-major over j
    float* sHj = sQj + 16*PADJ;         // [16][66]  h,  r-major over j
    float* srb = sHj + 16*PADJ;         // [64]
    int h = blockIdx.z, i0 = blockIdx.y * 64, j0 = blockIdx.x * 64;
    int tid = threadIdx.x;

    for (int idx = tid; idx < 4096; idx += 128) {
        int row = idx >> 6, d = idx & 63;
        sQa[d*PADJ + row] = g_Aq[(h*SS + i0 + row)*HDD + d];
        sKa[d*PADJ + row] = g_Ak[(h*SS + j0 + row)*HDD + d];
    }
    for (int idx = tid; idx < 1024; idx += 128) {
        int row = idx >> 4, r = idx & 15;
        sPi[r*64  + row] = g_P[(h*SS + i0 + row)*RR + r];
        sHi[r*64  + row] = g_h[(i0 + row)*RR + r];
        sQj[r*PADJ + row] = g_Q[(h*SS + j0 + row)*RR + r];
        sHj[r*PADJ + row] = g_h[(j0 + row)*RR + r];
    }
    if (tid < 64) srb[tid] = rbv[h*HDD + tid];
    __syncthreads();

    int ty = tid >> 3, tx = tid & 7;      // i = ty*4 + (0..3), j = tx*8 + (0..7)
    int ibase = ty*4, jbase = tx*8;
    ull acc3[16], acc12[16];
    #pragma unroll
    for (int o = 0; o < 16; o++) { acc3[o] = 0ull; acc12[o] = 0ull; }

    // ---- b1 + b2: rank-16, packed over j-pairs ----
    #pragma unroll
    for (int r = 0; r < 16; r++) {
        ull pi2[4], hi2[4], qj2[4], hj2[4];
        #pragma unroll
        for (int ii = 0; ii < 4; ii++) {
            float p = sPi[r*64 + ibase + ii]; pi2[ii] = pk2(p, p);
            float w = sHi[r*64 + ibase + ii]; hi2[ii] = pk2(w, w);
        }
        #pragma unroll
        for (int jp = 0; jp < 4; jp++) {
            qj2[jp] = *reinterpret_cast<const ull*>(&sQj[r*PADJ + jbase + 2*jp]);
            hj2[jp] = *reinterpret_cast<const ull*>(&sHj[r*PADJ + jbase + 2*jp]);
        }
        #pragma unroll
        for (int ii = 0; ii < 4; ii++)
            #pragma unroll
            for (int jp = 0; jp < 4; jp++) {
                int o = ii*4 + jp;
                acc12[o] = fma2(pi2[ii], hj2[jp], acc12[o]);
                acc12[o] = fma2(hi2[ii], qj2[jp], acc12[o]);
            }
    }

    // ---- b3: tanh(A_k[j,d] - A_q[i,d]) . rbv ----
    bool safe = (__uint_as_float(g_maxbits) <= 0.24f);   // |x| <= 0.48
    if (safe) {
        const ull c9p = pk2(C9, C9), c7p = pk2(C7, C7), c5p = pk2(C5, C5);
        const ull c3p = pk2(C3, C3), onep = pk2(1.0f, 1.0f);
        #pragma unroll 2
        for (int d = 0; d < 64; d++) {
            float rb = srb[d];
            ull rb2 = pk2(rb, rb);
            ull nq2[4], ka2[4];
            #pragma unroll
            for (int ii = 0; ii < 4; ii++) {
                float q = -sQa[d*PADJ + ibase + ii];
                nq2[ii] = pk2(q, q);
            }
            #pragma unroll
            for (int jp = 0; jp < 4; jp++)
                ka2[jp] = *reinterpret_cast<const ull*>(&sKa[d*PADJ + jbase + 2*jp]);
            #pragma unroll
            for (int ii = 0; ii < 4; ii++)
                #pragma unroll
                for (int jp = 0; jp < 4; jp++) {
                    int o = ii*4 + jp;
                    ull x  = add2(ka2[jp], nq2[ii]);
                    ull x2 = mul2(x, x);
                    ull p  = fma2(x2, c9p, c7p);
                    p = fma2(x2, p, c5p);
                    p = fma2(x2, p, c3p);
                    p = fma2(x2, p, onep);
                    acc3[o] = fma2(mul2(x, p), rb2, acc3[o]);
                }
        }
    } else {
        // exact cold path
        float a3lo[16], a3hi[16];
        #pragma unroll
        for (int o = 0; o < 16; o++) { a3lo[o] = 0.f; a3hi[o] = 0.f; }
        for (int d = 0; d < 64; d++) {
            float rb = srb[d];
            #pragma unroll
            for (int ii = 0; ii < 4; ii++) {
                float qa = sQa[d*PADJ + ibase + ii];
                #pragma unroll
                for (int jp = 0; jp < 4; jp++) {
                    float k0 = sKa[d*PADJ + jbase + 2*jp];
                    float k1 = sKa[d*PADJ + jbase + 2*jp + 1];
                    int o = ii*4 + jp;
                    a3lo[o] = fmaf(tanhf(k0 - qa), rb, a3lo[o]);
                    a3hi[o] = fmaf(tanhf(k1 - qa), rb, a3hi[o]);
                }
            }
        }
        #pragma unroll
        for (int o = 0; o < 16; o++) acc3[o] = pk2(a3lo[o], a3hi[o]);
    }

    float ca = gat[h] * 0.125f;   // g_attn / sqrt(64)
    float cr = grl[h];
    #pragma unroll
    for (int ii = 0; ii < 4; ii++) {
        int i = i0 + ibase + ii;
        float v[8];
        #pragma unroll
        for (int jp = 0; jp < 4; jp++) {
            float b12lo, b12hi, b3lo, b3hi;
            upk2(acc12[ii*4 + jp], b12lo, b12hi);
            upk2(acc3[ii*4 + jp],  b3lo,  b3hi);
            v[2*jp]     = fmaf(ca, b12lo, cr * b3lo);
            v[2*jp + 1] = fmaf(ca, b12hi, cr * b3hi);
        }
        float* dst = out + ((size_t)h*SS + i)*SS + j0 + jbase;
        *reinterpret_cast<float4*>(dst)     = make_float4(v[0], v[1], v[2], v[3]);
        *reinterpret_cast<float4*>(dst + 4) = make_float4(v[4], v[5], v[6], v[7]);
    }
}

// ----------------------------------------------------------------------------
extern "C" void kernel_launch(void* const* d_in, const int* in_sizes, int n_in,
                              void* d_out, int out_size) {
    const float* hidden = (const float*)d_in[0];
    const float* q_base = (const float*)d_in[1];
    const float* k_base = (const float*)d_in[2];
    const float* gamma  = (const float*)d_in[3];
    const float* beta   = (const float*)d_in[4];
    const float* W1     = (const float*)d_in[5];
    const float* W2     = (const float*)d_in[6];
    const float* Wq     = (const float*)d_in[7];
    const float* Wk     = (const float*)d_in[8];
    const float* Wv     = (const float*)d_in[9];
    const float* rbv    = (const float*)d_in[10];
    const float* gat    = (const float*)d_in[11];
    const float* grl    = (const float*)d_in[12];
    const float* gval   = (const float*)d_in[13];
    float* out = (float*)d_out;

    (void)in_sizes; (void)n_in; (void)out_size;

    static const size_t GAUGE_SMEM =
        (size_t)(2*64*PADJ + 2*16*64 + 2*16*PADJ + 64) * sizeof(float);
    cudaFuncSetAttribute(k_gauge, cudaFuncAttributeMaxDynamicSharedMemorySize,
                         (int)GAUGE_SMEM);

    k_ln_h  <<<SS, 256>>>(hidden, gamma, beta, W1);
    k_merge <<<72, 256>>>(Wq, Wk, Wv, W2);
    k_fieldA<<<SS, 256>>>(W2, gval, out + GAUGE_ELEMS);
    k_pq    <<<dim3(SS/16, HH), 256>>>(q_base, k_base);
    k_gauge <<<dim3(SS/64, SS/64, HH), 128, GAUGE_SMEM>>>(rbv, gat, grl, out);
}

// round 11
// speedup vs baseline: 1.0045x; 1.0045x over previous
#include <cuda_runtime.h>
#include <math.h>

#define SS 512
#define DD 768
#define HH 12
#define HDD 64
#define RR 16
#define GAUGE_ELEMS (HH*SS*SS)   // 3,145,728

typedef unsigned long long ull;

// ---------------- scratch (device globals; no allocation allowed) ------------
__device__ float g_h[SS*RR];                // [s][r]
__device__ float g_Aq[HH*SS*HDD];           // [h][s][d]
__device__ float g_Ak[HH*SS*HDD];
__device__ float g_Mq[HH*HDD*RR];           // [h][d][r]  = Wq @ W2q_h
__device__ float g_Mk[HH*HDD*RR];           // [h][d][r]  = Wk @ W2k_h
__device__ float g_Mv[DD*RR];               // [c][r]     = Wv @ W2v
__device__ float g_P[HH*SS*RR];             // [h][s][r]  = q_base @ Mk
__device__ float g_Q[HH*SS*RR];             // [h][s][r]  = k_base @ Mq
__device__ unsigned g_maxbits;

// degree-9 odd Taylor for tanh: exact to ~1e-5 for |x| <= 0.5
#define C3 (-0.333333333f)
#define C5 ( 0.133333333f)
#define C7 (-0.053968254f)
#define C9 ( 0.021869489f)

// ---------------- packed f32x2 helpers (sm_103a dual-fp32) -------------------
__device__ __forceinline__ ull pk2(float lo, float hi) {
    ull r; asm("mov.b64 %0,{%1,%2};" : "=l"(r) : "f"(lo), "f"(hi)); return r;
}
__device__ __forceinline__ void upk2(ull v, float& lo, float& hi) {
    asm("mov.b64 {%0,%1},%2;" : "=f"(lo), "=f"(hi) : "l"(v));
}
__device__ __forceinline__ ull fma2(ull a, ull b, ull c) {
    ull d; asm("fma.rn.f32x2 %0,%1,%2,%3;" : "=l"(d) : "l"(a), "l"(b), "l"(c)); return d;
}
__device__ __forceinline__ ull add2(ull a, ull b) {
    ull d; asm("add.rn.f32x2 %0,%1,%2;" : "=l"(d) : "l"(a), "l"(b)); return d;
}
__device__ __forceinline__ ull mul2(ull a, ull b) {
    ull d; asm("mul.rn.f32x2 %0,%1,%2;" : "=l"(d) : "l"(a), "l"(b)); return d;
}

// ------------------- K1: LayerNorm + h = silu(x @ W1^T) ---------------------
__global__ void k_ln_h(const float* __restrict__ hs, const float* __restrict__ gamma,
                       const float* __restrict__ beta, const float* __restrict__ W1) {
    int s = blockIdx.x, tid = threadIdx.x;
    if (blockIdx.x == 0 && tid == 0) g_maxbits = 0u;
    __shared__ float xs[DD];
    __shared__ float red[20];
    const float* row = hs + s*DD;
    float v0 = row[tid], v1 = row[tid+256], v2 = row[tid+512];
    float sum = v0+v1+v2, sq = v0*v0 + v1*v1 + v2*v2;
    #pragma unroll
    for (int o = 16; o; o >>= 1) {
        sum += __shfl_xor_sync(0xffffffffu, sum, o);
        sq  += __shfl_xor_sync(0xffffffffu, sq,  o);
    }
    int wid = tid >> 5, lid = tid & 31;
    if (lid == 0) { red[wid] = sum; red[wid+8] = sq; }
    __syncthreads();
    if (tid == 0) {
        float Sm = 0.f, Q = 0.f;
        for (int w = 0; w < 8; w++) { Sm += red[w]; Q += red[w+8]; }
        float mu  = Sm * (1.f/DD);
        float var = Q  * (1.f/DD) - mu*mu;
        red[16] = mu; red[17] = rsqrtf(var + 1e-5f);
    }
    __syncthreads();
    float mu = red[16], ri = red[17];
    xs[tid]     = (v0-mu)*ri*gamma[tid]     + beta[tid];
    xs[tid+256] = (v1-mu)*ri*gamma[tid+256] + beta[tid+256];
    xs[tid+512] = (v2-mu)*ri*gamma[tid+512] + beta[tid+512];
    __syncthreads();
    int r0 = wid * 2;
    float a0 = 0.f, a1 = 0.f;
    for (int e = lid; e < DD; e += 32) {
        float xv = xs[e];
        a0 = fmaf(xv, W1[r0*DD + e],     a0);
        a1 = fmaf(xv, W1[(r0+1)*DD + e], a1);
    }
    #pragma unroll
    for (int o = 16; o; o >>= 1) {
        a0 += __shfl_xor_sync(0xffffffffu, a0, o);
        a1 += __shfl_xor_sync(0xffffffffu, a1, o);
    }
    if (lid == 0) {
        g_h[s*RR + r0]     = a0 / (1.f + expf(-a0));
        g_h[s*RR + r0 + 1] = a1 / (1.f + expf(-a1));
    }
}

// ------- K2: merged weight products Mq, Mk (per head) and Mv (weights only) --
__global__ void k_merge(const float* __restrict__ Wq, const float* __restrict__ Wk,
                        const float* __restrict__ Wv, const float* __restrict__ W2) {
    int b = blockIdx.x, tid = threadIdx.x;
    if (b < 24) {
        // Mq (b<12) or Mk (b>=12): M[h][d][r] = sum_e W[d][e] * W2[off + h*64 + e][r]
        int h = (b < 12) ? b : b - 12;
        const float* Wx = (b < 12) ? Wq : Wk;
        float* dst = (b < 12) ? g_Mq : g_Mk;
        int w2off = (b < 12) ? 0 : 768;
        __shared__ float sW2[HDD*RR];   // [e][r]
        for (int idx = tid; idx < HDD*RR; idx += 256)
            sW2[idx] = W2[(size_t)(w2off + h*HDD + (idx >> 4))*RR + (idx & 15)];
        __syncthreads();
        for (int o = tid; o < HDD*RR; o += 256) {
            int d = o >> 4, r = o & 15;
            float acc = 0.f;
            #pragma unroll 8
            for (int e = 0; e < HDD; e++)
                acc = fmaf(Wx[d*HDD + e], sW2[e*RR + r], acc);
            dst[h*HDD*RR + o] = acc;
        }
    } else {
        // Mv: 48 blocks x 16 c-rows; Mv[c][r] = sum_e Wv[c][e] * W2[1536+e][r]
        int c0 = (b - 24) * 16;
        int c = c0 + (tid >> 4), r = tid & 15;
        float acc = 0.f;
        #pragma unroll 4
        for (int e = 0; e < DD; e++)
            acc = fmaf(Wv[(size_t)c*DD + e], W2[(size_t)(1536 + e)*RR + r], acc);
        g_Mv[c*RR + r] = acc;
    }
}

// -------- K3: A_q/A_k = h @ W2qk^T (head-major) + max|A|, delta_v fused -----
__global__ void k_fieldA(const float* __restrict__ W2, const float* __restrict__ gval,
                         float* __restrict__ out_dv) {
    int s = blockIdx.x, tid = threadIdx.x;
    __shared__ float hsh[RR];
    __shared__ float wmax[8];
    if (tid < RR) hsh[tid] = g_h[s*RR + tid];
    __syncthreads();
    float h0=hsh[0],h1=hsh[1],h2=hsh[2],h3=hsh[3],h4=hsh[4],h5=hsh[5],h6=hsh[6],h7=hsh[7];
    float h8=hsh[8],h9=hsh[9],hA=hsh[10],hB=hsh[11],hC=hsh[12],hD=hsh[13],hE=hsh[14],hF=hsh[15];
    float mx = 0.f;
    #pragma unroll
    for (int it = 0; it < 9; it++) {
        int c = it*256 + tid;
        const float* wrow = (c < 1536) ? (W2 + (size_t)c*RR) : (g_Mv + (size_t)(c-1536)*RR);
        const float4* wr = reinterpret_cast<const float4*>(wrow);
        float4 w0 = wr[0], w1 = wr[1], w2 = wr[2], w3 = wr[3];
        float acc = h0*w0.x + h1*w0.y + h2*w0.z + h3*w0.w
                  + h4*w1.x + h5*w1.y + h6*w1.z + h7*w1.w
                  + h8*w2.x + h9*w2.y + hA*w2.z + hB*w2.w
                  + hC*w3.x + hD*w3.y + hE*w3.z + hF*w3.w;
        if (c < 768) {
            int hh = c >> 6, d = c & 63;
            g_Aq[(hh*SS + s)*HDD + d] = acc;
            mx = fmaxf(mx, fabsf(acc));
        } else if (c < 1536) {
            int cc = c - 768; int hh = cc >> 6, d = cc & 63;
            g_Ak[(hh*SS + s)*HDD + d] = acc;
            mx = fmaxf(mx, fabsf(acc));
        } else {
            int cc = c - 1536;
            out_dv[(size_t)s*DD + cc] = tanhf(gval[cc]) * acc;
        }
    }
    #pragma unroll
    for (int o = 16; o; o >>= 1) mx = fmaxf(mx, __shfl_xor_sync(0xffffffffu, mx, o));
    if ((tid & 31) == 0) wmax[tid >> 5] = mx;
    __syncthreads();
    if (tid == 0) {
        float m = wmax[0];
        for (int w = 1; w < 8; w++) m = fmaxf(m, wmax[w]);
        atomicMax(&g_maxbits, __float_as_uint(m));
    }
}

// -------- K4: P = q_base @ Mk ; Q = k_base @ Mq (rank-16 projections) -------
__global__ void k_pq(const float* __restrict__ qb, const float* __restrict__ kb) {
    int h = blockIdx.y, s0 = blockIdx.x * 16, tid = threadIdx.x;
    __shared__ float sMk[HDD*RR], sMq[HDD*RR];
    for (int idx = tid; idx < HDD*RR; idx += 256) {
        sMk[idx] = g_Mk[h*HDD*RR + idx];
        sMq[idx] = g_Mq[h*HDD*RR + idx];
    }
    __syncthreads();
    int i = tid >> 4, r = tid & 15;
    int s = s0 + i;
    const float* qrow = qb + (size_t)(h*SS + s)*HDD;
    const float* krow = kb + (size_t)(h*SS + s)*HDD;
    float accP = 0.f, accQ = 0.f;
    #pragma unroll 8
    for (int d = 0; d < HDD; d++) {
        accP = fmaf(qrow[d], sMk[d*RR + r], accP);
        accQ = fmaf(krow[d], sMq[d*RR + r], accQ);
    }
    g_P[(h*SS + s)*RR + r] = accP;
    g_Q[(h*SS + s)*RR + r] = accQ;
}

// ---- K5: gauge[h,i,j] = ca*(b1+b2) + cr*b3, f32x2-packed, 64x64 tiles ------
#define PADJ 66
__global__ __launch_bounds__(128, 3)
void k_gauge(const float* __restrict__ rbv, const float* __restrict__ gat,
             const float* __restrict__ grl, float* __restrict__ out) {
    extern __shared__ float sm[];
    float* sQa = sm;                    // [64][66]  A_q, d-major over i
    float* sKa = sQa + 64*PADJ;         // [64][66]  A_k, d-major over j
    float* sPi = sKa + 64*PADJ;         // [16][64]  P,  r-major over i
    float* sHi = sPi + 16*64;           // [16][64]  h,  r-major over i
    float* sQj = sHi + 16*64;           // [16][66]  Q,  r-major over j
    float* sHj = sQj + 16*PADJ;         // [16][66]  h,  r-major over j
    float* srb = sHj + 16*PADJ;         // [64]
    int h = blockIdx.z, i0 = blockIdx.y * 64, j0 = blockIdx.x * 64;
    int tid = threadIdx.x;

    for (int idx = tid; idx < 4096; idx += 128) {
        int row = idx >> 6, d = idx & 63;
        sQa[d*PADJ + row] = g_Aq[(h*SS + i0 + row)*HDD + d];
        sKa[d*PADJ + row] = g_Ak[(h*SS + j0 + row)*HDD + d];
    }
    for (int idx = tid; idx < 1024; idx += 128) {
        int row = idx >> 4, r = idx & 15;
        sPi[r*64  + row] = g_P[(h*SS + i0 + row)*RR + r];
        sHi[r*64  + row] = g_h[(i0 + row)*RR + r];
        sQj[r*PADJ + row] = g_Q[(h*SS + j0 + row)*RR + r];
        sHj[r*PADJ + row] = g_h[(j0 + row)*RR + r];
    }
    if (tid < 64) srb[tid] = rbv[h*HDD + tid];
    __syncthreads();

    int ty = tid >> 3, tx = tid & 7;      // i = ty*4 + (0..3), j = tx*8 + (0..7)
    int ibase = ty*4, jbase = tx*8;
    ull acc3[16], acc12[16];
    #pragma unroll
    for (int o = 0; o < 16; o++) { acc3[o] = 0ull; acc12[o] = 0ull; }

    // ---- b1 + b2: rank-16, packed over j-pairs ----
    #pragma unroll
    for (int r = 0; r < 16; r++) {
        ull pi2[4], hi2[4], qj2[4], hj2[4];
        #pragma unroll
        for (int ii = 0; ii < 4; ii++) {
            float p = sPi[r*64 + ibase + ii]; pi2[ii] = pk2(p, p);
            float w = sHi[r*64 + ibase + ii]; hi2[ii] = pk2(w, w);
        }
        #pragma unroll
        for (int jp = 0; jp < 4; jp++) {
            qj2[jp] = *reinterpret_cast<const ull*>(&sQj[r*PADJ + jbase + 2*jp]);
            hj2[jp] = *reinterpret_cast<const ull*>(&sHj[r*PADJ + jbase + 2*jp]);
        }
        #pragma unroll
        for (int ii = 0; ii < 4; ii++)
            #pragma unroll
            for (int jp = 0; jp < 4; jp++) {
                int o = ii*4 + jp;
                acc12[o] = fma2(pi2[ii], hj2[jp], acc12[o]);
                acc12[o] = fma2(hi2[ii], qj2[jp], acc12[o]);
            }
    }

    // ---- b3: tanh(A_k[j,d] - A_q[i,d]) . rbv ----
    bool safe = (__uint_as_float(g_maxbits) <= 0.24f);   // |x| <= 0.48
    if (safe) {
        const ull c9p = pk2(C9, C9), c7p = pk2(C7, C7), c5p = pk2(C5, C5);
        const ull c3p = pk2(C3, C3), onep = pk2(1.0f, 1.0f);
        #pragma unroll 2
        for (int d = 0; d < 64; d++) {
            float rb = srb[d];
            ull rb2 = pk2(rb, rb);
            ull nq2[4], ka2[4];
            #pragma unroll
            for (int ii = 0; ii < 4; ii++) {
                float q = -sQa[d*PADJ + ibase + ii];
                nq2[ii] = pk2(q, q);
            }
            #pragma unroll
            for (int jp = 0; jp < 4; jp++)
                ka2[jp] = *reinterpret_cast<const ull*>(&sKa[d*PADJ + jbase + 2*jp]);
            #pragma unroll
            for (int ii = 0; ii < 4; ii++)
                #pragma unroll
                for (int jp = 0; jp < 4; jp++) {
                    int o = ii*4 + jp;
                    ull x  = add2(ka2[jp], nq2[ii]);
                    ull x2 = mul2(x, x);
                    ull p  = fma2(x2, c9p, c7p);
                    p = fma2(x2, p, c5p);
                    p = fma2(x2, p, c3p);
                    p = fma2(x2, p, onep);
                    acc3[o] = fma2(mul2(x, p), rb2, acc3[o]);
                }
        }
    } else {
        // exact cold path
        float a3lo[16], a3hi[16];
        #pragma unroll
        for (int o = 0; o < 16; o++) { a3lo[o] = 0.f; a3hi[o] = 0.f; }
        for (int d = 0; d < 64; d++) {
            float rb = srb[d];
            #pragma unroll
            for (int ii = 0; ii < 4; ii++) {
                float qa = sQa[d*PADJ + ibase + ii];
                #pragma unroll
                for (int jp = 0; jp < 4; jp++) {
                    float k0 = sKa[d*PADJ + jbase + 2*jp];
                    float k1 = sKa[d*PADJ + jbase + 2*jp + 1];
                    int o = ii*4 + jp;
                    a3lo[o] = fmaf(tanhf(k0 - qa), rb, a3lo[o]);
                    a3hi[o] = fmaf(tanhf(k1 - qa), rb, a3hi[o]);
                }
            }
        }
        #pragma unroll
        for (int o = 0; o < 16; o++) acc3[o] = pk2(a3lo[o], a3hi[o]);
    }

    float ca = gat[h] * 0.125f;   // g_attn / sqrt(64)
    float cr = grl[h];
    #pragma unroll
    for (int ii = 0; ii < 4; ii++) {
        int i = i0 + ibase + ii;
        float v[8];
        #pragma unroll
        for (int jp = 0; jp < 4; jp++) {
            float b12lo, b12hi, b3lo, b3hi;
            upk2(acc12[ii*4 + jp], b12lo, b12hi);
            upk2(acc3[ii*4 + jp],  b3lo,  b3hi);
            v[2*jp]     = fmaf(ca, b12lo, cr * b3lo);
            v[2*jp + 1] = fmaf(ca, b12hi, cr * b3hi);
        }
        float* dst = out + ((size_t)h*SS + i)*SS + j0 + jbase;
        *reinterpret_cast<float4*>(dst)     = make_float4(v[0], v[1], v[2], v[3]);
        *reinterpret_cast<float4*>(dst + 4) = make_float4(v[4], v[5], v[6], v[7]);
    }
}

// ----------------------------------------------------------------------------
extern "C" void kernel_launch(void* const* d_in, const int* in_sizes, int n_in,
                              void* d_out, int out_size) {
    const float* hidden = (const float*)d_in[0];
    const float* q_base = (const float*)d_in[1];
    const float* k_base = (const float*)d_in[2];
    const float* gamma  = (const float*)d_in[3];
    const float* beta   = (const float*)d_in[4];
    const float* W1     = (const float*)d_in[5];
    const float* W2     = (const float*)d_in[6];
    const float* Wq     = (const float*)d_in[7];
    const float* Wk     = (const float*)d_in[8];
    const float* Wv     = (const float*)d_in[9];
    const float* rbv    = (const float*)d_in[10];
    const float* gat    = (const float*)d_in[11];
    const float* grl    = (const float*)d_in[12];
    const float* gval   = (const float*)d_in[13];
    float* out = (float*)d_out;

    (void)in_sizes; (void)n_in; (void)out_size;

    static const size_t GAUGE_SMEM =
        (size_t)(2*64*PADJ + 2*16*64 + 2*16*PADJ + 64) * sizeof(float);
    cudaFuncSetAttribute(k_gauge, cudaFuncAttributeMaxDynamicSharedMemorySize,
                         (int)GAUGE_SMEM);

    k_ln_h  <<<SS, 256>>>(hidden, gamma, beta, W1);
    k_merge <<<72, 256>>>(Wq, Wk, Wv, W2);
    k_fieldA<<<SS, 256>>>(W2, gval, out + GAUGE_ELEMS);
    k_pq    <<<dim3(SS/16, HH), 256>>>(q_base, k_base);
    k_gauge <<<dim3(SS/64, SS/64, HH), 128, GAUGE_SMEM>>>(rbv, gat, grl, out);
}